// round 4
// baseline (speedup 1.0000x reference)
#include <cuda_runtime.h>
#include <math.h>

// Problem constants
#define NB   2
#define NS   2048
#define NH   16
#define ND   64
#define NHID 1024
#define NCK  64      // chunk size
#define NNC  32      // chunks per sequence (NS/NCK)
#define NBH  32      // NB*NH
#define PST  68      // padded smem row stride (floats)

// Scratch (static device globals -- no allocation allowed)
__device__ float g_qr[NBH * NS * ND];          // rotated Q, [bh][s][d]
__device__ float g_kr[NBH * NS * ND];          // rotated K, [bh][s][d]
__device__ float g_A [NBH * NNC * ND * ND];    // per-chunk state contributions
__device__ float g_St[NBH * NNC * ND * ND];    // prefix-scanned states (state BEFORE chunk c)

__device__ __forceinline__ double head_lg(int h) {
    // gammas = 1 - exp(linspace(log(1/32), log(1/512), 16));  return log(gamma_h)
    const double L0 = -3.4657359027997265;   // log(1/32)
    const double L1 = -6.2383246250395075;   // log(1/512)
    double g = 1.0 - exp(L0 + (L1 - L0) * ((double)h / 15.0));
    return log(g);
}

// ---------------------------------------------------------------------------
// Kernel 1: xPos rotation of Q (upscale) and K (downscale) into [bh][s][d]
// One thread per (b,h,s,pair i), i in [0,32)
// ---------------------------------------------------------------------------
__global__ __launch_bounds__(256)
void rope_kernel(const float* __restrict__ Q, const float* __restrict__ K) {
    __shared__ float s_invf[32];
    __shared__ float s_bs[32];
    int tid = threadIdx.x;
    if (tid < 32) {
        s_invf[tid] = (float)(1.0 / pow(10000.0, (double)tid / 32.0));
        s_bs[tid]   = (2.0f * (float)tid + 0.4f * 64.0f) / (1.4f * 64.0f);
    }
    __syncthreads();

    int idx = blockIdx.x * 256 + tid;          // [0, NB*NH*NS*32)
    int i  = idx & 31;
    int s  = (idx >> 5) & (NS - 1);
    int bh = idx >> 16;                        // 5 + 11 bits
    int h  = bh & (NH - 1);
    int b  = bh >> 4;

    float pos = (float)s;
    float ang = pos * s_invf[i];
    float sn, cs;
    sincosf(ang, &sn, &cs);
    float sc = powf(s_bs[i], pos * (1.0f / 512.0f));
    float iv = 1.0f / sc;

    int gin = (b * NS + s) * NHID + h * ND + 2 * i;
    float q0 = Q[gin], q1 = Q[gin + 1];
    float k0 = K[gin], k1 = K[gin + 1];

    float cq = cs * sc, sq = sn * sc;
    float ck = cs * iv, sk = sn * iv;

    int gout = (bh * NS + s) * ND + 2 * i;
    g_qr[gout]     = q0 * cq - q1 * sq;
    g_qr[gout + 1] = q1 * cq + q0 * sq;
    g_kr[gout]     = k0 * ck - k1 * sk;
    g_kr[gout + 1] = k1 * ck + k0 * sk;
}

// ---------------------------------------------------------------------------
// Kernel 2: per-chunk state contribution A_c[d][e] = sum_j gamma^(C-j) k[j][d] v[j][e]
// Grid (NNC, NH, NB), 256 threads, 16x16 thread grid, 4x4 micro-tile
// ---------------------------------------------------------------------------
__global__ __launch_bounds__(256)
void passA_kernel(const float* __restrict__ V) {
    __shared__ float ks[NCK][PST];
    __shared__ float vs[NCK][PST];
    __shared__ float wr[NCK];

    int c = blockIdx.x, h = blockIdx.y, b = blockIdx.z;
    int bh = b * NH + h;
    int tid = threadIdx.x;

    if (tid < NCK) {
        double lg = head_lg(h);
        wr[tid] = (float)exp(lg * (double)(NCK - tid));   // gamma^(C-j), j=tid
    }
    __syncthreads();

    int c0 = c * NCK;
    const float* kg = g_kr + (bh * NS + c0) * ND;
    const float* vg = V + (b * NS + c0) * NHID + h * ND;

#pragma unroll
    for (int t = 0; t < 16; ++t) {
        int idx = tid + t * 256;
        int r = idx >> 6, d = idx & 63;
        ks[r][d] = kg[r * ND + d] * wr[r];
        vs[r][d] = vg[r * NHID + d];
    }
    __syncthreads();

    int ty = tid >> 4, tx = tid & 15;
    float acc[4][4];
#pragma unroll
    for (int di = 0; di < 4; ++di)
#pragma unroll
        for (int ei = 0; ei < 4; ++ei) acc[di][ei] = 0.0f;

#pragma unroll 8
    for (int j = 0; j < NCK; ++j) {
        float a0 = ks[j][4 * ty + 0];
        float a1 = ks[j][4 * ty + 1];
        float a2 = ks[j][4 * ty + 2];
        float a3 = ks[j][4 * ty + 3];
        float4 bv = *(const float4*)&vs[j][4 * tx];
        acc[0][0] += a0 * bv.x; acc[0][1] += a0 * bv.y; acc[0][2] += a0 * bv.z; acc[0][3] += a0 * bv.w;
        acc[1][0] += a1 * bv.x; acc[1][1] += a1 * bv.y; acc[1][2] += a1 * bv.z; acc[1][3] += a1 * bv.w;
        acc[2][0] += a2 * bv.x; acc[2][1] += a2 * bv.y; acc[2][2] += a2 * bv.z; acc[2][3] += a2 * bv.w;
        acc[3][0] += a3 * bv.x; acc[3][1] += a3 * bv.y; acc[3][2] += a3 * bv.z; acc[3][3] += a3 * bv.w;
    }

    float* ag = g_A + ((size_t)bh * NNC + c) * ND * ND;
#pragma unroll
    for (int di = 0; di < 4; ++di) {
        float4 w = make_float4(acc[di][0], acc[di][1], acc[di][2], acc[di][3]);
        *(float4*)&ag[(4 * ty + di) * ND + 4 * tx] = w;
    }
}

// ---------------------------------------------------------------------------
// Kernel 3: sequential prefix scan over chunks: St_{c+1} = gamma^C * St_c + A_c
// g_St[c] holds the state BEFORE chunk c. Grid NBH, 256 threads x 16 elems.
// ---------------------------------------------------------------------------
__global__ __launch_bounds__(256)
void scan_kernel() {
    int bh = blockIdx.x;
    int h = bh & (NH - 1);
    int tid = threadIdx.x;
    double lg = head_lg(h);
    float dec = (float)exp(lg * (double)NCK);

    float st[16];
#pragma unroll
    for (int k = 0; k < 16; ++k) st[k] = 0.0f;

    size_t base = (size_t)bh * NNC * ND * ND;
    for (int c = 0; c < NNC; ++c) {
        size_t off = base + (size_t)c * ND * ND + tid;
#pragma unroll
        for (int k = 0; k < 16; ++k) {
            g_St[off + k * 256] = st[k];
            st[k] = st[k] * dec + g_A[off + k * 256];
        }
    }
}

// ---------------------------------------------------------------------------
// Kernel 4: per-chunk output.
//   q' = gamma^i q,  k' = gamma^{-j} k   (i,j local positions in chunk)
//   P[i][j] = (q'_i . k'_j) for j<=i else 0        (intra-chunk, decay folded)
//   O[i][e] = sum_j P[i][j] v[j][e] + sum_d q'[i][d] St[d][e]
// Grid (NNC, NH, NB), 256 threads, dynamic smem ~85.5KB
// ---------------------------------------------------------------------------
extern __shared__ float sm_c[];

__global__ __launch_bounds__(256)
void passC_kernel(const float* __restrict__ V, float* __restrict__ out) {
    float* qs  = sm_c;                  // [NCK][PST]
    float* ksT = qs + NCK * PST;        // [ND][NCK], xor-swizzled in float4 units
    float* ps  = ksT + ND * NCK;        // [NCK][NCK]
    float* vs  = ps + NCK * NCK;        // [NCK][PST]
    float* sts = vs + NCK * PST;        // [ND][PST]
    float* wq  = sts + ND * PST;        // [NCK]  gamma^i
    float* wk  = wq + NCK;              // [NCK]  gamma^{-j}

    int c = blockIdx.x, h = blockIdx.y, b = blockIdx.z;
    int bh = b * NH + h;
    int tid = threadIdx.x;

    if (tid < NCK) {
        double lg = head_lg(h);
        wq[tid] = (float)exp(lg * (double)tid);
        wk[tid] = (float)exp(-lg * (double)tid);
    }
    __syncthreads();

    int c0 = c * NCK;
    const float* qg  = g_qr + (bh * NS + c0) * ND;
    const float* kg  = g_kr + (bh * NS + c0) * ND;
    const float* vg  = V + (b * NS + c0) * NHID + h * ND;
    const float* stg = g_St + ((size_t)bh * NNC + c) * ND * ND;

#pragma unroll
    for (int t = 0; t < 16; ++t) {
        int idx = tid + t * 256;
        int r = idx >> 6, d = idx & 63;
        qs[r * PST + d] = qg[r * ND + d] * wq[r];
        float kv = kg[r * ND + d] * wk[r];
        // transpose + xor swizzle: logical (row d, col r) -> conflict-light layout
        ksT[d * NCK + (((r >> 2) ^ (d & 15)) << 2) + (r & 3)] = kv;
        vs[r * PST + d] = vg[r * NHID + d];
        sts[r * PST + d] = stg[idx];     // here r = state row d', d = column e
    }
    __syncthreads();

    int ty = tid >> 4, tx = tid & 15;
    int i0 = 4 * ty, j0 = 4 * tx;

    // GEMM1: P = Q' K'^T
    float acc[4][4];
#pragma unroll
    for (int di = 0; di < 4; ++di)
#pragma unroll
        for (int ei = 0; ei < 4; ++ei) acc[di][ei] = 0.0f;

#pragma unroll 8
    for (int d = 0; d < ND; ++d) {
        float a0 = qs[(i0 + 0) * PST + d];
        float a1 = qs[(i0 + 1) * PST + d];
        float a2 = qs[(i0 + 2) * PST + d];
        float a3 = qs[(i0 + 3) * PST + d];
        float4 bv = *(const float4*)&ksT[d * NCK + ((tx ^ (d & 15)) << 2)];
        acc[0][0] += a0 * bv.x; acc[0][1] += a0 * bv.y; acc[0][2] += a0 * bv.z; acc[0][3] += a0 * bv.w;
        acc[1][0] += a1 * bv.x; acc[1][1] += a1 * bv.y; acc[1][2] += a1 * bv.z; acc[1][3] += a1 * bv.w;
        acc[2][0] += a2 * bv.x; acc[2][1] += a2 * bv.y; acc[2][2] += a2 * bv.z; acc[2][3] += a2 * bv.w;
        acc[3][0] += a3 * bv.x; acc[3][1] += a3 * bv.y; acc[3][2] += a3 * bv.z; acc[3][3] += a3 * bv.w;
    }

    // causal mask (within-chunk) + stage P in smem
#pragma unroll
    for (int di = 0; di < 4; ++di) {
        int ii = i0 + di;
        float4 w;
        w.x = (j0 + 0 <= ii) ? acc[di][0] : 0.0f;
        w.y = (j0 + 1 <= ii) ? acc[di][1] : 0.0f;
        w.z = (j0 + 2 <= ii) ? acc[di][2] : 0.0f;
        w.w = (j0 + 3 <= ii) ? acc[di][3] : 0.0f;
        *(float4*)&ps[ii * NCK + j0] = w;
    }
    __syncthreads();

    // GEMM2: O = P V  +  Q' St
    float o[4][4];
#pragma unroll
    for (int di = 0; di < 4; ++di)
#pragma unroll
        for (int ei = 0; ei < 4; ++ei) o[di][ei] = 0.0f;

#pragma unroll 8
    for (int j = 0; j < NCK; ++j) {
        float a0 = ps[(i0 + 0) * NCK + j];
        float a1 = ps[(i0 + 1) * NCK + j];
        float a2 = ps[(i0 + 2) * NCK + j];
        float a3 = ps[(i0 + 3) * NCK + j];
        float4 bv = *(const float4*)&vs[j * PST + j0];
        o[0][0] += a0 * bv.x; o[0][1] += a0 * bv.y; o[0][2] += a0 * bv.z; o[0][3] += a0 * bv.w;
        o[1][0] += a1 * bv.x; o[1][1] += a1 * bv.y; o[1][2] += a1 * bv.z; o[1][3] += a1 * bv.w;
        o[2][0] += a2 * bv.x; o[2][1] += a2 * bv.y; o[2][2] += a2 * bv.z; o[2][3] += a2 * bv.w;
        o[3][0] += a3 * bv.x; o[3][1] += a3 * bv.y; o[3][2] += a3 * bv.z; o[3][3] += a3 * bv.w;
    }
#pragma unroll 8
    for (int d = 0; d < ND; ++d) {
        float a0 = qs[(i0 + 0) * PST + d];
        float a1 = qs[(i0 + 1) * PST + d];
        float a2 = qs[(i0 + 2) * PST + d];
        float a3 = qs[(i0 + 3) * PST + d];
        float4 bv = *(const float4*)&sts[d * PST + j0];
        o[0][0] += a0 * bv.x; o[0][1] += a0 * bv.y; o[0][2] += a0 * bv.z; o[0][3] += a0 * bv.w;
        o[1][0] += a1 * bv.x; o[1][1] += a1 * bv.y; o[1][2] += a1 * bv.z; o[1][3] += a1 * bv.w;
        o[2][0] += a2 * bv.x; o[2][1] += a2 * bv.y; o[2][2] += a2 * bv.z; o[2][3] += a2 * bv.w;
        o[3][0] += a3 * bv.x; o[3][1] += a3 * bv.y; o[3][2] += a3 * bv.z; o[3][3] += a3 * bv.w;
    }

    float* og = out + (b * NS + c0) * NHID + h * ND;
#pragma unroll
    for (int di = 0; di < 4; ++di) {
        float4 w = make_float4(o[di][0], o[di][1], o[di][2], o[di][3]);
        *(float4*)&og[(i0 + di) * NHID + j0] = w;
    }
}

// ---------------------------------------------------------------------------
extern "C" void kernel_launch(void* const* d_in, const int* in_sizes, int n_in,
                              void* d_out, int out_size) {
    (void)in_sizes; (void)n_in; (void)out_size;
    const float* Q = (const float*)d_in[0];
    const float* K = (const float*)d_in[1];
    const float* V = (const float*)d_in[2];
    float* out = (float*)d_out;

    rope_kernel<<<(NB * NH * NS * 32) / 256, 256>>>(Q, K);

    dim3 grid(NNC, NH, NB);
    passA_kernel<<<grid, 256>>>(V);
    scan_kernel<<<NBH, 256>>>();

    size_t shm = (size_t)(NCK * PST + ND * NCK + NCK * NCK + NCK * PST + ND * PST + 2 * NCK) * sizeof(float);
    cudaFuncSetAttribute(passC_kernel, cudaFuncAttributeMaxDynamicSharedMemorySize, (int)shm);
    passC_kernel<<<grid, 256, shm>>>(V, out);
}

// round 5
// speedup vs baseline: 1.0003x; 1.0003x over previous
#include <cuda_runtime.h>
#include <math.h>

// Problem constants
#define NB   2
#define NS   2048
#define NH   16
#define ND   64
#define NHID 1024
#define NCK  64      // chunk size
#define NNC  32      // chunks per sequence (NS/NCK)
#define NBH  32      // NB*NH
#define PST  68      // padded smem row stride (floats)

// Scratch (static device globals -- no allocation allowed)
__device__ float g_qr[NBH * NS * ND];          // rotated Q, [bh][s][d]
__device__ float g_kr[NBH * NS * ND];          // rotated K, [bh][s][d]
__device__ float g_A [NBH * NNC * ND * ND];    // per-chunk state contributions
__device__ float g_St[NBH * NNC * ND * ND];    // prefix-scanned states (state BEFORE chunk c)

__device__ __forceinline__ double head_lg(int h) {
    // gammas = 1 - exp(linspace(log(1/32), log(1/512), 16));  return log(gamma_h)
    const double L0 = -3.4657359027997265;   // log(1/32)
    const double L1 = -6.2383246250395075;   // log(1/512)
    double g = 1.0 - exp(L0 + (L1 - L0) * ((double)h / 15.0));
    return log(g);
}

// ---------------------------------------------------------------------------
// Kernel 1: xPos rotation of Q (upscale) and K (downscale) into [bh][s][d]
// One thread per (b,h,s,pair i), i in [0,32)
// ---------------------------------------------------------------------------
__global__ __launch_bounds__(256)
void rope_kernel(const float* __restrict__ Q, const float* __restrict__ K) {
    __shared__ float s_invf[32];
    __shared__ float s_bs[32];
    int tid = threadIdx.x;
    if (tid < 32) {
        s_invf[tid] = (float)(1.0 / pow(10000.0, (double)tid / 32.0));
        s_bs[tid]   = (2.0f * (float)tid + 0.4f * 64.0f) / (1.4f * 64.0f);
    }
    __syncthreads();

    int idx = blockIdx.x * 256 + tid;          // [0, NB*NH*NS*32)
    int i  = idx & 31;
    int s  = (idx >> 5) & (NS - 1);
    int bh = idx >> 16;                        // 5 + 11 bits
    int h  = bh & (NH - 1);
    int b  = bh >> 4;

    float pos = (float)s;
    float ang = pos * s_invf[i];
    float sn, cs;
    sincosf(ang, &sn, &cs);
    float sc = powf(s_bs[i], pos * (1.0f / 512.0f));
    float iv = 1.0f / sc;

    int gin = (b * NS + s) * NHID + h * ND + 2 * i;
    float q0 = Q[gin], q1 = Q[gin + 1];
    float k0 = K[gin], k1 = K[gin + 1];

    float cq = cs * sc, sq = sn * sc;
    float ck = cs * iv, sk = sn * iv;

    int gout = (bh * NS + s) * ND + 2 * i;
    g_qr[gout]     = q0 * cq - q1 * sq;
    g_qr[gout + 1] = q1 * cq + q0 * sq;
    g_kr[gout]     = k0 * ck - k1 * sk;
    g_kr[gout + 1] = k1 * ck + k0 * sk;
}

// ---------------------------------------------------------------------------
// Kernel 2: per-chunk state contribution A_c[d][e] = sum_j gamma^(C-j) k[j][d] v[j][e]
// Grid (NNC, NH, NB), 256 threads, 16x16 thread grid, 4x4 micro-tile
// ---------------------------------------------------------------------------
__global__ __launch_bounds__(256)
void passA_kernel(const float* __restrict__ V) {
    __shared__ float ks[NCK][PST];
    __shared__ float vs[NCK][PST];
    __shared__ float wr[NCK];

    int c = blockIdx.x, h = blockIdx.y, b = blockIdx.z;
    int bh = b * NH + h;
    int tid = threadIdx.x;

    if (tid < NCK) {
        double lg = head_lg(h);
        wr[tid] = (float)exp(lg * (double)(NCK - tid));   // gamma^(C-j), j=tid
    }
    __syncthreads();

    int c0 = c * NCK;
    const float* kg = g_kr + (bh * NS + c0) * ND;
    const float* vg = V + (b * NS + c0) * NHID + h * ND;

#pragma unroll
    for (int t = 0; t < 16; ++t) {
        int idx = tid + t * 256;
        int r = idx >> 6, d = idx & 63;
        ks[r][d] = kg[r * ND + d] * wr[r];
        vs[r][d] = vg[r * NHID + d];
    }
    __syncthreads();

    int ty = tid >> 4, tx = tid & 15;
    float acc[4][4];
#pragma unroll
    for (int di = 0; di < 4; ++di)
#pragma unroll
        for (int ei = 0; ei < 4; ++ei) acc[di][ei] = 0.0f;

#pragma unroll 8
    for (int j = 0; j < NCK; ++j) {
        float a0 = ks[j][4 * ty + 0];
        float a1 = ks[j][4 * ty + 1];
        float a2 = ks[j][4 * ty + 2];
        float a3 = ks[j][4 * ty + 3];
        float4 bv = *(const float4*)&vs[j][4 * tx];
        acc[0][0] += a0 * bv.x; acc[0][1] += a0 * bv.y; acc[0][2] += a0 * bv.z; acc[0][3] += a0 * bv.w;
        acc[1][0] += a1 * bv.x; acc[1][1] += a1 * bv.y; acc[1][2] += a1 * bv.z; acc[1][3] += a1 * bv.w;
        acc[2][0] += a2 * bv.x; acc[2][1] += a2 * bv.y; acc[2][2] += a2 * bv.z; acc[2][3] += a2 * bv.w;
        acc[3][0] += a3 * bv.x; acc[3][1] += a3 * bv.y; acc[3][2] += a3 * bv.z; acc[3][3] += a3 * bv.w;
    }

    float* ag = g_A + ((size_t)bh * NNC + c) * ND * ND;
#pragma unroll
    for (int di = 0; di < 4; ++di) {
        float4 w = make_float4(acc[di][0], acc[di][1], acc[di][2], acc[di][3]);
        *(float4*)&ag[(4 * ty + di) * ND + 4 * tx] = w;
    }
}

// ---------------------------------------------------------------------------
// Kernel 3: sequential prefix scan over chunks: St_{c+1} = gamma^C * St_c + A_c
// g_St[c] holds the state BEFORE chunk c. Grid NBH, 256 threads x 16 elems.
// ---------------------------------------------------------------------------
__global__ __launch_bounds__(256)
void scan_kernel() {
    int bh = blockIdx.x;
    int h = bh & (NH - 1);
    int tid = threadIdx.x;
    double lg = head_lg(h);
    float dec = (float)exp(lg * (double)NCK);

    float st[16];
#pragma unroll
    for (int k = 0; k < 16; ++k) st[k] = 0.0f;

    size_t base = (size_t)bh * NNC * ND * ND;
    for (int c = 0; c < NNC; ++c) {
        size_t off = base + (size_t)c * ND * ND + tid;
#pragma unroll
        for (int k = 0; k < 16; ++k) {
            g_St[off + k * 256] = st[k];
            st[k] = st[k] * dec + g_A[off + k * 256];
        }
    }
}

// ---------------------------------------------------------------------------
// Kernel 4: per-chunk output.
//   q' = gamma^i q,  k' = gamma^{-j} k   (i,j local positions in chunk)
//   P[i][j] = (q'_i . k'_j) for j<=i else 0        (intra-chunk, decay folded)
//   O[i][e] = sum_j P[i][j] v[j][e] + sum_d q'[i][d] St[d][e]
// Grid (NNC, NH, NB), 256 threads, dynamic smem ~85.5KB
// ---------------------------------------------------------------------------
extern __shared__ float sm_c[];

__global__ __launch_bounds__(256)
void passC_kernel(const float* __restrict__ V, float* __restrict__ out) {
    float* qs  = sm_c;                  // [NCK][PST]
    float* ksT = qs + NCK * PST;        // [ND][NCK], xor-swizzled in float4 units
    float* ps  = ksT + ND * NCK;        // [NCK][NCK]
    float* vs  = ps + NCK * NCK;        // [NCK][PST]
    float* sts = vs + NCK * PST;        // [ND][PST]
    float* wq  = sts + ND * PST;        // [NCK]  gamma^i
    float* wk  = wq + NCK;              // [NCK]  gamma^{-j}

    int c = blockIdx.x, h = blockIdx.y, b = blockIdx.z;
    int bh = b * NH + h;
    int tid = threadIdx.x;

    if (tid < NCK) {
        double lg = head_lg(h);
        wq[tid] = (float)exp(lg * (double)tid);
        wk[tid] = (float)exp(-lg * (double)tid);
    }
    __syncthreads();

    int c0 = c * NCK;
    const float* qg  = g_qr + (bh * NS + c0) * ND;
    const float* kg  = g_kr + (bh * NS + c0) * ND;
    const float* vg  = V + (b * NS + c0) * NHID + h * ND;
    const float* stg = g_St + ((size_t)bh * NNC + c) * ND * ND;

#pragma unroll
    for (int t = 0; t < 16; ++t) {
        int idx = tid + t * 256;
        int r = idx >> 6, d = idx & 63;
        qs[r * PST + d] = qg[r * ND + d] * wq[r];
        float kv = kg[r * ND + d] * wk[r];
        // transpose + xor swizzle: logical (row d, col r) -> conflict-light layout
        ksT[d * NCK + (((r >> 2) ^ (d & 15)) << 2) + (r & 3)] = kv;
        vs[r * PST + d] = vg[r * NHID + d];
        sts[r * PST + d] = stg[idx];     // here r = state row d', d = column e
    }
    __syncthreads();

    int ty = tid >> 4, tx = tid & 15;
    int i0 = 4 * ty, j0 = 4 * tx;

    // GEMM1: P = Q' K'^T
    float acc[4][4];
#pragma unroll
    for (int di = 0; di < 4; ++di)
#pragma unroll
        for (int ei = 0; ei < 4; ++ei) acc[di][ei] = 0.0f;

#pragma unroll 8
    for (int d = 0; d < ND; ++d) {
        float a0 = qs[(i0 + 0) * PST + d];
        float a1 = qs[(i0 + 1) * PST + d];
        float a2 = qs[(i0 + 2) * PST + d];
        float a3 = qs[(i0 + 3) * PST + d];
        float4 bv = *(const float4*)&ksT[d * NCK + ((tx ^ (d & 15)) << 2)];
        acc[0][0] += a0 * bv.x; acc[0][1] += a0 * bv.y; acc[0][2] += a0 * bv.z; acc[0][3] += a0 * bv.w;
        acc[1][0] += a1 * bv.x; acc[1][1] += a1 * bv.y; acc[1][2] += a1 * bv.z; acc[1][3] += a1 * bv.w;
        acc[2][0] += a2 * bv.x; acc[2][1] += a2 * bv.y; acc[2][2] += a2 * bv.z; acc[2][3] += a2 * bv.w;
        acc[3][0] += a3 * bv.x; acc[3][1] += a3 * bv.y; acc[3][2] += a3 * bv.z; acc[3][3] += a3 * bv.w;
    }

    // causal mask (within-chunk) + stage P in smem
#pragma unroll
    for (int di = 0; di < 4; ++di) {
        int ii = i0 + di;
        float4 w;
        w.x = (j0 + 0 <= ii) ? acc[di][0] : 0.0f;
        w.y = (j0 + 1 <= ii) ? acc[di][1] : 0.0f;
        w.z = (j0 + 2 <= ii) ? acc[di][2] : 0.0f;
        w.w = (j0 + 3 <= ii) ? acc[di][3] : 0.0f;
        *(float4*)&ps[ii * NCK + j0] = w;
    }
    __syncthreads();

    // GEMM2: O = P V  +  Q' St
    float o[4][4];
#pragma unroll
    for (int di = 0; di < 4; ++di)
#pragma unroll
        for (int ei = 0; ei < 4; ++ei) o[di][ei] = 0.0f;

#pragma unroll 8
    for (int j = 0; j < NCK; ++j) {
        float a0 = ps[(i0 + 0) * NCK + j];
        float a1 = ps[(i0 + 1) * NCK + j];
        float a2 = ps[(i0 + 2) * NCK + j];
        float a3 = ps[(i0 + 3) * NCK + j];
        float4 bv = *(const float4*)&vs[j * PST + j0];
        o[0][0] += a0 * bv.x; o[0][1] += a0 * bv.y; o[0][2] += a0 * bv.z; o[0][3] += a0 * bv.w;
        o[1][0] += a1 * bv.x; o[1][1] += a1 * bv.y; o[1][2] += a1 * bv.z; o[1][3] += a1 * bv.w;
        o[2][0] += a2 * bv.x; o[2][1] += a2 * bv.y; o[2][2] += a2 * bv.z; o[2][3] += a2 * bv.w;
        o[3][0] += a3 * bv.x; o[3][1] += a3 * bv.y; o[3][2] += a3 * bv.z; o[3][3] += a3 * bv.w;
    }
#pragma unroll 8
    for (int d = 0; d < ND; ++d) {
        float a0 = qs[(i0 + 0) * PST + d];
        float a1 = qs[(i0 + 1) * PST + d];
        float a2 = qs[(i0 + 2) * PST + d];
        float a3 = qs[(i0 + 3) * PST + d];
        float4 bv = *(const float4*)&sts[d * PST + j0];
        o[0][0] += a0 * bv.x; o[0][1] += a0 * bv.y; o[0][2] += a0 * bv.z; o[0][3] += a0 * bv.w;
        o[1][0] += a1 * bv.x; o[1][1] += a1 * bv.y; o[1][2] += a1 * bv.z; o[1][3] += a1 * bv.w;
        o[2][0] += a2 * bv.x; o[2][1] += a2 * bv.y; o[2][2] += a2 * bv.z; o[2][3] += a2 * bv.w;
        o[3][0] += a3 * bv.x; o[3][1] += a3 * bv.y; o[3][2] += a3 * bv.z; o[3][3] += a3 * bv.w;
    }

    float* og = out + (b * NS + c0) * NHID + h * ND;
#pragma unroll
    for (int di = 0; di < 4; ++di) {
        float4 w = make_float4(o[di][0], o[di][1], o[di][2], o[di][3]);
        *(float4*)&og[(i0 + di) * NHID + j0] = w;
    }
}

// ---------------------------------------------------------------------------
extern "C" void kernel_launch(void* const* d_in, const int* in_sizes, int n_in,
                              void* d_out, int out_size) {
    (void)in_sizes; (void)n_in; (void)out_size;
    const float* Q = (const float*)d_in[0];
    const float* K = (const float*)d_in[1];
    const float* V = (const float*)d_in[2];
    float* out = (float*)d_out;

    rope_kernel<<<(NB * NH * NS * 32) / 256, 256>>>(Q, K);

    dim3 grid(NNC, NH, NB);
    passA_kernel<<<grid, 256>>>(V);
    scan_kernel<<<NBH, 256>>>();

    size_t shm = (size_t)(NCK * PST + ND * NCK + NCK * NCK + NCK * PST + ND * PST + 2 * NCK) * sizeof(float);
    cudaFuncSetAttribute(passC_kernel, cudaFuncAttributeMaxDynamicSharedMemorySize, (int)shm);
    passC_kernel<<<grid, 256, shm>>>(V, out);
}

// round 6
// speedup vs baseline: 1.0037x; 1.0033x over previous
#include <cuda_runtime.h>
#include <math.h>

// Problem constants
#define NB   2
#define NS   2048
#define NH   16
#define ND   64
#define NHID 1024
#define NCK  64      // chunk size
#define NNC  32      // chunks per sequence (NS/NCK)
#define NBH  32      // NB*NH
#define PST  68      // padded smem row stride (floats)

// Scratch (static device globals -- no allocation allowed)
__device__ float g_qr[NBH * NS * ND];          // rotated Q, [bh][s][d]
__device__ float g_kr[NBH * NS * ND];          // rotated K, [bh][s][d]
__device__ float g_A [NBH * NNC * ND * ND];    // per-chunk state contributions
__device__ float g_St[NBH * NNC * ND * ND];    // prefix-scanned states (state BEFORE chunk c)

__device__ __forceinline__ double head_lg(int h) {
    // gammas = 1 - exp(linspace(log(1/32), log(1/512), 16));  return log(gamma_h)
    const double L0 = -3.4657359027997265;   // log(1/32)
    const double L1 = -6.2383246250395075;   // log(1/512)
    double g = 1.0 - exp(L0 + (L1 - L0) * ((double)h / 15.0));
    return log(g);
}

// ---------------------------------------------------------------------------
// Kernel 1: xPos rotation of Q (upscale) and K (downscale) into [bh][s][d]
// One thread per (b,h,s,pair i), i in [0,32)
// ---------------------------------------------------------------------------
__global__ __launch_bounds__(256)
void rope_kernel(const float* __restrict__ Q, const float* __restrict__ K) {
    __shared__ float s_invf[32];
    __shared__ float s_bs[32];
    int tid = threadIdx.x;
    if (tid < 32) {
        s_invf[tid] = (float)(1.0 / pow(10000.0, (double)tid / 32.0));
        s_bs[tid]   = (2.0f * (float)tid + 0.4f * 64.0f) / (1.4f * 64.0f);
    }
    __syncthreads();

    int idx = blockIdx.x * 256 + tid;          // [0, NB*NH*NS*32)
    int i  = idx & 31;
    int s  = (idx >> 5) & (NS - 1);
    int bh = idx >> 16;                        // 5 + 11 bits
    int h  = bh & (NH - 1);
    int b  = bh >> 4;

    float pos = (float)s;
    float ang = pos * s_invf[i];
    float sn, cs;
    sincosf(ang, &sn, &cs);
    float sc = powf(s_bs[i], pos * (1.0f / 512.0f));
    float iv = 1.0f / sc;

    int gin = (b * NS + s) * NHID + h * ND + 2 * i;
    float q0 = Q[gin], q1 = Q[gin + 1];
    float k0 = K[gin], k1 = K[gin + 1];

    float cq = cs * sc, sq = sn * sc;
    float ck = cs * iv, sk = sn * iv;

    int gout = (bh * NS + s) * ND + 2 * i;
    g_qr[gout]     = q0 * cq - q1 * sq;
    g_qr[gout + 1] = q1 * cq + q0 * sq;
    g_kr[gout]     = k0 * ck - k1 * sk;
    g_kr[gout + 1] = k1 * ck + k0 * sk;
}

// ---------------------------------------------------------------------------
// Kernel 2: per-chunk state contribution A_c[d][e] = sum_j gamma^(C-j) k[j][d] v[j][e]
// Grid (NNC, NH, NB), 256 threads, 16x16 thread grid, 4x4 micro-tile
// ---------------------------------------------------------------------------
__global__ __launch_bounds__(256)
void passA_kernel(const float* __restrict__ V) {
    __shared__ float ks[NCK][PST];
    __shared__ float vs[NCK][PST];
    __shared__ float wr[NCK];

    int c = blockIdx.x, h = blockIdx.y, b = blockIdx.z;
    int bh = b * NH + h;
    int tid = threadIdx.x;

    if (tid < NCK) {
        double lg = head_lg(h);
        wr[tid] = (float)exp(lg * (double)(NCK - tid));   // gamma^(C-j), j=tid
    }
    __syncthreads();

    int c0 = c * NCK;
    const float* kg = g_kr + (bh * NS + c0) * ND;
    const float* vg = V + (b * NS + c0) * NHID + h * ND;

#pragma unroll
    for (int t = 0; t < 16; ++t) {
        int idx = tid + t * 256;
        int r = idx >> 6, d = idx & 63;
        ks[r][d] = kg[r * ND + d] * wr[r];
        vs[r][d] = vg[r * NHID + d];
    }
    __syncthreads();

    int ty = tid >> 4, tx = tid & 15;
    float acc[4][4];
#pragma unroll
    for (int di = 0; di < 4; ++di)
#pragma unroll
        for (int ei = 0; ei < 4; ++ei) acc[di][ei] = 0.0f;

#pragma unroll 8
    for (int j = 0; j < NCK; ++j) {
        float a0 = ks[j][4 * ty + 0];
        float a1 = ks[j][4 * ty + 1];
        float a2 = ks[j][4 * ty + 2];
        float a3 = ks[j][4 * ty + 3];
        float4 bv = *(const float4*)&vs[j][4 * tx];
        acc[0][0] += a0 * bv.x; acc[0][1] += a0 * bv.y; acc[0][2] += a0 * bv.z; acc[0][3] += a0 * bv.w;
        acc[1][0] += a1 * bv.x; acc[1][1] += a1 * bv.y; acc[1][2] += a1 * bv.z; acc[1][3] += a1 * bv.w;
        acc[2][0] += a2 * bv.x; acc[2][1] += a2 * bv.y; acc[2][2] += a2 * bv.z; acc[2][3] += a2 * bv.w;
        acc[3][0] += a3 * bv.x; acc[3][1] += a3 * bv.y; acc[3][2] += a3 * bv.z; acc[3][3] += a3 * bv.w;
    }

    float* ag = g_A + ((size_t)bh * NNC + c) * ND * ND;
#pragma unroll
    for (int di = 0; di < 4; ++di) {
        float4 w = make_float4(acc[di][0], acc[di][1], acc[di][2], acc[di][3]);
        *(float4*)&ag[(4 * ty + di) * ND + 4 * tx] = w;
    }
}

// ---------------------------------------------------------------------------
// Kernel 3: sequential prefix scan over chunks: St_{c+1} = gamma^C * St_c + A_c
// g_St[c] holds the state BEFORE chunk c. Grid NBH, 256 threads x 16 elems.
// ---------------------------------------------------------------------------
__global__ __launch_bounds__(256)
void scan_kernel() {
    int bh = blockIdx.x;
    int h = bh & (NH - 1);
    int tid = threadIdx.x;
    double lg = head_lg(h);
    float dec = (float)exp(lg * (double)NCK);

    float st[16];
#pragma unroll
    for (int k = 0; k < 16; ++k) st[k] = 0.0f;

    size_t base = (size_t)bh * NNC * ND * ND;
    for (int c = 0; c < NNC; ++c) {
        size_t off = base + (size_t)c * ND * ND + tid;
#pragma unroll
        for (int k = 0; k < 16; ++k) {
            g_St[off + k * 256] = st[k];
            st[k] = st[k] * dec + g_A[off + k * 256];
        }
    }
}

// ---------------------------------------------------------------------------
// Kernel 4: per-chunk output.
//   q' = gamma^i q,  k' = gamma^{-j} k   (i,j local positions in chunk)
//   P[i][j] = (q'_i . k'_j) for j<=i else 0        (intra-chunk, decay folded)
//   O[i][e] = sum_j P[i][j] v[j][e] + sum_d q'[i][d] St[d][e]
// Grid (NNC, NH, NB), 256 threads, dynamic smem ~85.5KB
// ---------------------------------------------------------------------------
extern __shared__ float sm_c[];

__global__ __launch_bounds__(256)
void passC_kernel(const float* __restrict__ V, float* __restrict__ out) {
    float* qs  = sm_c;                  // [NCK][PST]
    float* ksT = qs + NCK * PST;        // [ND][NCK], xor-swizzled in float4 units
    float* ps  = ksT + ND * NCK;        // [NCK][NCK]
    float* vs  = ps + NCK * NCK;        // [NCK][PST]
    float* sts = vs + NCK * PST;        // [ND][PST]
    float* wq  = sts + ND * PST;        // [NCK]  gamma^i
    float* wk  = wq + NCK;              // [NCK]  gamma^{-j}

    int c = blockIdx.x, h = blockIdx.y, b = blockIdx.z;
    int bh = b * NH + h;
    int tid = threadIdx.x;

    if (tid < NCK) {
        double lg = head_lg(h);
        wq[tid] = (float)exp(lg * (double)tid);
        wk[tid] = (float)exp(-lg * (double)tid);
    }
    __syncthreads();

    int c0 = c * NCK;
    const float* qg  = g_qr + (bh * NS + c0) * ND;
    const float* kg  = g_kr + (bh * NS + c0) * ND;
    const float* vg  = V + (b * NS + c0) * NHID + h * ND;
    const float* stg = g_St + ((size_t)bh * NNC + c) * ND * ND;

#pragma unroll
    for (int t = 0; t < 16; ++t) {
        int idx = tid + t * 256;
        int r = idx >> 6, d = idx & 63;
        qs[r * PST + d] = qg[r * ND + d] * wq[r];
        float kv = kg[r * ND + d] * wk[r];
        // transpose + xor swizzle: logical (row d, col r) -> conflict-light layout
        ksT[d * NCK + (((r >> 2) ^ (d & 15)) << 2) + (r & 3)] = kv;
        vs[r * PST + d] = vg[r * NHID + d];
        sts[r * PST + d] = stg[idx];     // here r = state row d', d = column e
    }
    __syncthreads();

    int ty = tid >> 4, tx = tid & 15;
    int i0 = 4 * ty, j0 = 4 * tx;

    // GEMM1: P = Q' K'^T
    float acc[4][4];
#pragma unroll
    for (int di = 0; di < 4; ++di)
#pragma unroll
        for (int ei = 0; ei < 4; ++ei) acc[di][ei] = 0.0f;

#pragma unroll 8
    for (int d = 0; d < ND; ++d) {
        float a0 = qs[(i0 + 0) * PST + d];
        float a1 = qs[(i0 + 1) * PST + d];
        float a2 = qs[(i0 + 2) * PST + d];
        float a3 = qs[(i0 + 3) * PST + d];
        float4 bv = *(const float4*)&ksT[d * NCK + ((tx ^ (d & 15)) << 2)];
        acc[0][0] += a0 * bv.x; acc[0][1] += a0 * bv.y; acc[0][2] += a0 * bv.z; acc[0][3] += a0 * bv.w;
        acc[1][0] += a1 * bv.x; acc[1][1] += a1 * bv.y; acc[1][2] += a1 * bv.z; acc[1][3] += a1 * bv.w;
        acc[2][0] += a2 * bv.x; acc[2][1] += a2 * bv.y; acc[2][2] += a2 * bv.z; acc[2][3] += a2 * bv.w;
        acc[3][0] += a3 * bv.x; acc[3][1] += a3 * bv.y; acc[3][2] += a3 * bv.z; acc[3][3] += a3 * bv.w;
    }

    // causal mask (within-chunk) + stage P in smem
#pragma unroll
    for (int di = 0; di < 4; ++di) {
        int ii = i0 + di;
        float4 w;
        w.x = (j0 + 0 <= ii) ? acc[di][0] : 0.0f;
        w.y = (j0 + 1 <= ii) ? acc[di][1] : 0.0f;
        w.z = (j0 + 2 <= ii) ? acc[di][2] : 0.0f;
        w.w = (j0 + 3 <= ii) ? acc[di][3] : 0.0f;
        *(float4*)&ps[ii * NCK + j0] = w;
    }
    __syncthreads();

    // GEMM2: O = P V  +  Q' St
    float o[4][4];
#pragma unroll
    for (int di = 0; di < 4; ++di)
#pragma unroll
        for (int ei = 0; ei < 4; ++ei) o[di][ei] = 0.0f;

#pragma unroll 8
    for (int j = 0; j < NCK; ++j) {
        float a0 = ps[(i0 + 0) * NCK + j];
        float a1 = ps[(i0 + 1) * NCK + j];
        float a2 = ps[(i0 + 2) * NCK + j];
        float a3 = ps[(i0 + 3) * NCK + j];
        float4 bv = *(const float4*)&vs[j * PST + j0];
        o[0][0] += a0 * bv.x; o[0][1] += a0 * bv.y; o[0][2] += a0 * bv.z; o[0][3] += a0 * bv.w;
        o[1][0] += a1 * bv.x; o[1][1] += a1 * bv.y; o[1][2] += a1 * bv.z; o[1][3] += a1 * bv.w;
        o[2][0] += a2 * bv.x; o[2][1] += a2 * bv.y; o[2][2] += a2 * bv.z; o[2][3] += a2 * bv.w;
        o[3][0] += a3 * bv.x; o[3][1] += a3 * bv.y; o[3][2] += a3 * bv.z; o[3][3] += a3 * bv.w;
    }
#pragma unroll 8
    for (int d = 0; d < ND; ++d) {
        float a0 = qs[(i0 + 0) * PST + d];
        float a1 = qs[(i0 + 1) * PST + d];
        float a2 = qs[(i0 + 2) * PST + d];
        float a3 = qs[(i0 + 3) * PST + d];
        float4 bv = *(const float4*)&sts[d * PST + j0];
        o[0][0] += a0 * bv.x; o[0][1] += a0 * bv.y; o[0][2] += a0 * bv.z; o[0][3] += a0 * bv.w;
        o[1][0] += a1 * bv.x; o[1][1] += a1 * bv.y; o[1][2] += a1 * bv.z; o[1][3] += a1 * bv.w;
        o[2][0] += a2 * bv.x; o[2][1] += a2 * bv.y; o[2][2] += a2 * bv.z; o[2][3] += a2 * bv.w;
        o[3][0] += a3 * bv.x; o[3][1] += a3 * bv.y; o[3][2] += a3 * bv.z; o[3][3] += a3 * bv.w;
    }

    float* og = out + (b * NS + c0) * NHID + h * ND;
#pragma unroll
    for (int di = 0; di < 4; ++di) {
        float4 w = make_float4(o[di][0], o[di][1], o[di][2], o[di][3]);
        *(float4*)&og[(i0 + di) * NHID + j0] = w;
    }
}

// ---------------------------------------------------------------------------
extern "C" void kernel_launch(void* const* d_in, const int* in_sizes, int n_in,
                              void* d_out, int out_size) {
    (void)in_sizes; (void)n_in; (void)out_size;
    const float* Q = (const float*)d_in[0];
    const float* K = (const float*)d_in[1];
    const float* V = (const float*)d_in[2];
    float* out = (float*)d_out;

    rope_kernel<<<(NB * NH * NS * 32) / 256, 256>>>(Q, K);

    dim3 grid(NNC, NH, NB);
    passA_kernel<<<grid, 256>>>(V);
    scan_kernel<<<NBH, 256>>>();

    size_t shm = (size_t)(NCK * PST + ND * NCK + NCK * NCK + NCK * PST + ND * PST + 2 * NCK) * sizeof(float);
    cudaFuncSetAttribute(passC_kernel, cudaFuncAttributeMaxDynamicSharedMemorySize, (int)shm);
    passC_kernel<<<grid, 256, shm>>>(V, out);
}